// round 16
// baseline (speedup 1.0000x reference)
#include <cuda_runtime.h>

#define S      112
#define PLANE  (S * S)        // 12544
#define P4     (PLANE / 4)    // 3136
#define NB     64
#define NC     64
#define KH     56             // folded K (DCT even/odd symmetry)
#define WP     57             // pitch for W56 / Te / To
#define TP     113            // pitch for T in sT

#define NTH    896            // 448 compute + 448 fill threads in dct blocks
#define NCT    448
#define NBLK   148            // one wave, one block per SM
#define NDCT   128

// fill region: channels [2,64) of every batch, float4 units
#define SLAB4   (62 * P4)          // 194432
#define TOTAL4  (NB * SLAB4)       // 12443648
#define CHUNK4  84079              // ceil(TOTAL4/148): equal per-SM share

// Mask facts (xs[i] = i XOR 2, s = xs[i]+xs[j], mul = 14):
//  c==0 keeps s < 196; c==1 keeps s >= 196 (only i,j in [84,111]); c>=2 -> 1e-8.

// smem layout (floats)
#define SM_W   0
#define SM_A   6384
#define SM_AO  (SM_A + 6384)
#define SM_T   (SM_A + 12768)
#define SM_FLOATS (SM_T + 12656)   // 31808 floats = 127232 bytes

#define BARC() asm volatile("bar.sync 1, %0;" :: "n"(NCT) : "memory")

__device__ __forceinline__ void fill_one(float4* __restrict__ out4, int idx,
                                         const float4& f) {
    const int b   = idx / SLAB4;
    const int off = idx - b * SLAB4;
    __stcs(&out4[(size_t)b * (NC * P4) + 2 * P4 + off], f);
}

// Fill [start,end) with 1e-8; 4 independent STG.128 in flight per warp.
__device__ __forceinline__ void fill_range(float4* __restrict__ out4,
                                           int start, int end,
                                           int lane, int nlanes) {
    const float v = 1e-8f;
    const float4 f = make_float4(v, v, v, v);
    int idx = start + lane;
    #pragma unroll 1
    for (; idx + 3 * nlanes < end; idx += 4 * nlanes) {
        fill_one(out4, idx,              f);
        fill_one(out4, idx +     nlanes, f);
        fill_one(out4, idx + 2 * nlanes, f);
        fill_one(out4, idx + 3 * nlanes, f);
    }
    #pragma unroll 1
    for (; idx < end; idx += nlanes) fill_one(out4, idx, f);
}

__global__ void __launch_bounds__(NTH, 1)
fused_kernel(const float* __restrict__ x,
             const float* __restrict__ W,
             float* __restrict__ out) {
    const int bx  = blockIdx.x;
    const int tid = threadIdx.x;

    const int fstart = bx * CHUNK4;
    const int fend   = min(fstart + CHUNK4, TOTAL4);

    if (bx >= NDCT) {               // pure fill blocks: all 896 threads
        fill_range((float4*)out, fstart, fend, tid, NTH);
        return;
    }
    if (tid >= NCT) {               // fill warps inside dct blocks (14 warps)
        fill_range((float4*)out, fstart, fend, tid - NCT, NTH - NCT);
        return;
    }

    // ---- dct compute path: warps 0..13, named barrier only ----
    extern __shared__ float sm[];
    float* sW56 = sm + SM_W;
    float* sAe  = sm + SM_A;    // Xe / Te
    float* sAo  = sm + SM_AO;   // Xo / To
    float* sT   = sm + SM_T;

    const int c  = (bx >= 64);
    const int b  = c ? (bx - 64) : bx;
    const int ty = tid >> 4;               // 0..27
    const int tx = tid & 15;               // 0..15

    // GEMM2 mapping (rows free, same-parity cols)
    const int i0 = ty * 4;
    const int colbase = ((tx >> 1) * 14) + (tx & 1);

    // GEMM1 mapping (4 same-parity rows, 7 contiguous cols)
    const bool odd1  = (ty >= 14);
    const int  rbase = odd1 ? (8 * (ty - 14) + 1) : (8 * ty);   // rows rbase+2r
    const int  j1    = tx * 7;

    float* ob = out + (size_t)(b * NC + c) * PLANE;

    // c==1: fill the plane except the 28x28 corner.
    if (c) {
        const float v = 1e-8f;
        const float4 f = make_float4(v, v, v, v);
        float4* o4 = (float4*)ob;
        for (int i = tid; i < P4; i += NCT) {
            const int row = i / 28;
            const int j4  = (i - row * 28) * 4;
            if (row >= 84 && j4 >= 84) continue;
            __stcs(&o4[i], f);
        }
    }

    // Load W[:,0:56] (pitch 57) and X plane (contiguous into sT).
    for (int idx = tid; idx < S * KH; idx += NCT) {
        const int r = idx / KH, k = idx - r * KH;
        sW56[r * WP + k] = W[r * S + k];
    }
    {
        const float4* xs = (const float4*)(x + (size_t)(b * NC + c) * PLANE);
        float4* xd = (float4*)sT;
        for (int i = tid; i < P4; i += NCT) xd[i] = xs[i];
    }
    BARC();

    // Fold 1: Xe/Xo[k][j] = X[k][j] +/- X[111-k][j], k<56 (pitch 112).
    for (int idx = tid; idx < KH * S; idx += NCT) {
        const int k = idx / S, j = idx - k * S;
        const float x0 = sT[k * S + j];
        const float x1 = sT[(111 - k) * S + j];
        sAe[k * S + j] = x0 + x1;
        sAo[k * S + j] = x0 - x1;
    }
    BARC();   // X consumed; sT free for T

    // GEMM1: T[i][j] = sum_{k<56} W[i,k] * Xsel[k][j], 4 same-parity rows.
    const bool act1 = (c == 0) || (ty >= 10 && ty < 14) || (ty >= 24);
    if (act1) {
        const float* Xsel = odd1 ? sAo : sAe;
        float acc[4][7];
        #pragma unroll
        for (int r = 0; r < 4; r++)
            #pragma unroll
            for (int q = 0; q < 7; q++) acc[r][q] = 0.0f;

        for (int k = 0; k < KH; k++) {
            float a[4];
            #pragma unroll
            for (int r = 0; r < 4; r++) a[r] = sW56[(rbase + 2 * r) * WP + k];
            float bb[7];
            #pragma unroll
            for (int q = 0; q < 7; q++) bb[q] = Xsel[k * S + j1 + q];
            #pragma unroll
            for (int r = 0; r < 4; r++)
                #pragma unroll
                for (int q = 0; q < 7; q++)
                    acc[r][q] = fmaf(a[r], bb[q], acc[r][q]);
        }
        #pragma unroll
        for (int r = 0; r < 4; r++)
            #pragma unroll
            for (int q = 0; q < 7; q++)
                sT[(rbase + 2 * r) * TP + j1 + q] = acc[r][q];
    }
    BARC();   // T complete

    // Fold 2: Te/To[i][l] = T[i][l] +/- T[i][111-l], l<56 (pitch 57).
    if (c == 0) {
        for (int idx = tid; idx < S * KH; idx += NCT) {
            const int i = idx / KH, l = idx - i * KH;
            const float t0 = sT[i * TP + l];
            const float t1 = sT[i * TP + 111 - l];
            sAe[i * WP + l] = t0 + t1;
            sAo[i * WP + l] = t0 - t1;
        }
    } else {
        for (int idx = tid; idx < 28 * KH; idx += NCT) {
            const int r = idx / KH, l = idx - r * KH;
            const int i = 84 + r;
            const float t0 = sT[i * TP + l];
            const float t1 = sT[i * TP + 111 - l];
            sAe[i * WP + l] = t0 + t1;
            sAo[i * WP + l] = t0 - t1;
        }
    }
    BARC();

    // GEMM2: Y[i][j] = sum_{l<56} W[j,l] * (j even ? Te : To)[i][l], masked write.
    const bool act2 = (c == 0) || (ty >= 21 && tx >= 12);
    if (act2) {
        const float* Tsel = (tx & 1) ? sAo : sAe;
        float acc[4][7];
        #pragma unroll
        for (int r = 0; r < 4; r++)
            #pragma unroll
            for (int q = 0; q < 7; q++) acc[r][q] = 0.0f;

        for (int l = 0; l < KH; l++) {
            float a[4];
            #pragma unroll
            for (int r = 0; r < 4; r++) a[r] = Tsel[(i0 + r) * WP + l];
            float bb[7];
            #pragma unroll
            for (int q = 0; q < 7; q++) bb[q] = sW56[(colbase + 2 * q) * WP + l];
            #pragma unroll
            for (int r = 0; r < 4; r++)
                #pragma unroll
                for (int q = 0; q < 7; q++)
                    acc[r][q] = fmaf(a[r], bb[q], acc[r][q]);
        }

        #pragma unroll
        for (int r = 0; r < 4; r++) {
            const int i  = i0 + r;
            const int si = i ^ 2;
            #pragma unroll
            for (int q = 0; q < 7; q++) {
                const int j = colbase + 2 * q;
                const int s = si + (j ^ 2);
                const bool keep = c ? (s >= 196) : (s < 196);
                ob[i * S + j] = keep ? acc[r][q] : 1e-8f;
            }
        }
    }
}

// ---------------------------------------------------------------------------
extern "C" void kernel_launch(void* const* d_in, const int* in_sizes, int n_in,
                              void* d_out, int out_size) {
    const float* x = (const float*)d_in[0];   // [64, 64, 112, 112]
    const float* W = (const float*)d_in[1];   // [112, 112]
    float* out = (float*)d_out;

    const int smem = SM_FLOATS * (int)sizeof(float);   // 127232
    cudaFuncSetAttribute(fused_kernel, cudaFuncAttributeMaxDynamicSharedMemorySize, smem);
    fused_kernel<<<NBLK, NTH, smem>>>(x, W, out);
}

// round 17
// speedup vs baseline: 1.1725x; 1.1725x over previous
#include <cuda_runtime.h>

#define S      112
#define PLANE  (S * S)        // 12544
#define P4     (PLANE / 4)    // 3136
#define NB     64
#define NC     64
#define KH     56             // folded K (DCT even/odd symmetry)
#define WP     57             // pitch for W56 / Te / To
#define TP     113            // pitch for T in sT

#define NTH    896            // 448 compute + 448 fill threads in dct blocks
#define NCT    448
#define NBLK   148            // one wave, one block per SM
#define NDCT   128

// fill region: channels [2,64) of every batch, float4 units
#define SLAB4   (62 * P4)          // 194432
#define TOTAL4  (NB * SLAB4)       // 12443648
#define TILE4   4096               // 64KB tiles; TOTAL4 = 3038 * TILE4 exactly
#define NTILES  (TOTAL4 / TILE4)   // 3038

// Mask facts (xs[i] = i XOR 2, s = xs[i]+xs[j], mul = 14):
//  c==0 keeps s < 196; c==1 keeps s >= 196 (only i,j in [84,111]); c>=2 -> 1e-8.

// smem layout (floats)
#define SM_W   0
#define SM_A   6384
#define SM_AO  (SM_A + 6384)
#define SM_T   (SM_A + 12768)
#define SM_FLOATS (SM_T + 12656)   // 31808 floats = 127232 bytes

#define BARC() asm volatile("bar.sync 1, %0;" :: "n"(NCT) : "memory")

__device__ unsigned int g_ctr;

__global__ void reset_ctr() { g_ctr = 0; }

// Warp-cooperative work-stealing fill: grab 64KB tiles until pool is empty.
__device__ __forceinline__ void fill_steal(float4* __restrict__ out4, int lane) {
    const float v = 1e-8f;
    const float4 f = make_float4(v, v, v, v);
    for (;;) {
        unsigned int t;
        if (lane == 0) t = atomicAdd(&g_ctr, 1u);
        t = __shfl_sync(0xffffffffu, t, 0);
        if (t >= NTILES) return;
        const int base = (int)t * TILE4;
        #pragma unroll 1
        for (int i = lane; i < TILE4; i += 32) {
            const int idx = base + i;
            const int b   = idx / SLAB4;
            const int off = idx - b * SLAB4;
            __stcs(&out4[(size_t)b * (NC * P4) + 2 * P4 + off], f);
        }
    }
}

__global__ void __launch_bounds__(NTH, 1)
fused_kernel(const float* __restrict__ x,
             const float* __restrict__ W,
             float* __restrict__ out) {
    const int bx   = blockIdx.x;
    const int tid  = threadIdx.x;
    const int lane = tid & 31;

    if (bx >= NDCT || tid >= NCT) {     // pure fill blocks + fill warps
        fill_steal((float4*)out, lane);
        return;
    }

    // ---- dct compute path: warps 0..13, named barrier only ----
    extern __shared__ float sm[];
    float* sW56 = sm + SM_W;
    float* sAe  = sm + SM_A;    // Xe / Te
    float* sAo  = sm + SM_AO;   // Xo / To
    float* sT   = sm + SM_T;

    const int c  = (bx >= 64);
    const int b  = c ? (bx - 64) : bx;
    const int ty = tid >> 4;               // 0..27
    const int tx = tid & 15;               // 0..15

    // GEMM2 mapping (rows free, same-parity cols)
    const int i0 = ty * 4;
    const int colbase = ((tx >> 1) * 14) + (tx & 1);

    // GEMM1 mapping (4 same-parity rows, 7 contiguous cols)
    const bool odd1  = (ty >= 14);
    const int  rbase = odd1 ? (8 * (ty - 14) + 1) : (8 * ty);   // rows rbase+2r
    const int  j1    = tx * 7;

    float* ob = out + (size_t)(b * NC + c) * PLANE;

    // c==1: fill the plane except the 28x28 corner.
    if (c) {
        const float v = 1e-8f;
        const float4 f = make_float4(v, v, v, v);
        float4* o4 = (float4*)ob;
        for (int i = tid; i < P4; i += NCT) {
            const int row = i / 28;
            const int j4  = (i - row * 28) * 4;
            if (row >= 84 && j4 >= 84) continue;
            __stcs(&o4[i], f);
        }
    }

    // Load W[:,0:56] (pitch 57) and X plane (contiguous into sT).
    for (int idx = tid; idx < S * KH; idx += NCT) {
        const int r = idx / KH, k = idx - r * KH;
        sW56[r * WP + k] = W[r * S + k];
    }
    {
        const float4* xs = (const float4*)(x + (size_t)(b * NC + c) * PLANE);
        float4* xd = (float4*)sT;
        for (int i = tid; i < P4; i += NCT) xd[i] = xs[i];
    }
    BARC();

    // Fold 1: Xe/Xo[k][j] = X[k][j] +/- X[111-k][j], k<56 (pitch 112).
    for (int idx = tid; idx < KH * S; idx += NCT) {
        const int k = idx / S, j = idx - k * S;
        const float x0 = sT[k * S + j];
        const float x1 = sT[(111 - k) * S + j];
        sAe[k * S + j] = x0 + x1;
        sAo[k * S + j] = x0 - x1;
    }
    BARC();   // X consumed; sT free for T

    // GEMM1: T[i][j] = sum_{k<56} W[i,k] * Xsel[k][j], 4 same-parity rows.
    const bool act1 = (c == 0) || (ty >= 10 && ty < 14) || (ty >= 24);
    if (act1) {
        const float* Xsel = odd1 ? sAo : sAe;
        float acc[4][7];
        #pragma unroll
        for (int r = 0; r < 4; r++)
            #pragma unroll
            for (int q = 0; q < 7; q++) acc[r][q] = 0.0f;

        for (int k = 0; k < KH; k++) {
            float a[4];
            #pragma unroll
            for (int r = 0; r < 4; r++) a[r] = sW56[(rbase + 2 * r) * WP + k];
            float bb[7];
            #pragma unroll
            for (int q = 0; q < 7; q++) bb[q] = Xsel[k * S + j1 + q];
            #pragma unroll
            for (int r = 0; r < 4; r++)
                #pragma unroll
                for (int q = 0; q < 7; q++)
                    acc[r][q] = fmaf(a[r], bb[q], acc[r][q]);
        }
        #pragma unroll
        for (int r = 0; r < 4; r++)
            #pragma unroll
            for (int q = 0; q < 7; q++)
                sT[(rbase + 2 * r) * TP + j1 + q] = acc[r][q];
    }
    BARC();   // T complete

    // Fold 2: Te/To[i][l] = T[i][l] +/- T[i][111-l], l<56 (pitch 57).
    if (c == 0) {
        for (int idx = tid; idx < S * KH; idx += NCT) {
            const int i = idx / KH, l = idx - i * KH;
            const float t0 = sT[i * TP + l];
            const float t1 = sT[i * TP + 111 - l];
            sAe[i * WP + l] = t0 + t1;
            sAo[i * WP + l] = t0 - t1;
        }
    } else {
        for (int idx = tid; idx < 28 * KH; idx += NCT) {
            const int r = idx / KH, l = idx - r * KH;
            const int i = 84 + r;
            const float t0 = sT[i * TP + l];
            const float t1 = sT[i * TP + 111 - l];
            sAe[i * WP + l] = t0 + t1;
            sAo[i * WP + l] = t0 - t1;
        }
    }
    BARC();

    // GEMM2: Y[i][j] = sum_{l<56} W[j,l] * (j even ? Te : To)[i][l], masked write.
    const bool act2 = (c == 0) || (ty >= 21 && tx >= 12);
    if (act2) {
        const float* Tsel = (tx & 1) ? sAo : sAe;
        float acc[4][7];
        #pragma unroll
        for (int r = 0; r < 4; r++)
            #pragma unroll
            for (int q = 0; q < 7; q++) acc[r][q] = 0.0f;

        for (int l = 0; l < KH; l++) {
            float a[4];
            #pragma unroll
            for (int r = 0; r < 4; r++) a[r] = Tsel[(i0 + r) * WP + l];
            float bb[7];
            #pragma unroll
            for (int q = 0; q < 7; q++) bb[q] = sW56[(colbase + 2 * q) * WP + l];
            #pragma unroll
            for (int r = 0; r < 4; r++)
                #pragma unroll
                for (int q = 0; q < 7; q++)
                    acc[r][q] = fmaf(a[r], bb[q], acc[r][q]);
        }

        #pragma unroll
        for (int r = 0; r < 4; r++) {
            const int i  = i0 + r;
            const int si = i ^ 2;
            #pragma unroll
            for (int q = 0; q < 7; q++) {
                const int j = colbase + 2 * q;
                const int s = si + (j ^ 2);
                const bool keep = c ? (s >= 196) : (s < 196);
                ob[i * S + j] = keep ? acc[r][q] : 1e-8f;
            }
        }
    }

    // Compute warps done -> join the fill pool (no barrier needed; smem is
    // not written by anyone after this point).
    __syncwarp();
    fill_steal((float4*)out, lane);
}

// ---------------------------------------------------------------------------
extern "C" void kernel_launch(void* const* d_in, const int* in_sizes, int n_in,
                              void* d_out, int out_size) {
    const float* x = (const float*)d_in[0];   // [64, 64, 112, 112]
    const float* W = (const float*)d_in[1];   // [112, 112]
    float* out = (float*)d_out;

    const int smem = SM_FLOATS * (int)sizeof(float);   // 127232
    cudaFuncSetAttribute(fused_kernel, cudaFuncAttributeMaxDynamicSharedMemorySize, smem);

    reset_ctr<<<1, 1>>>();
    fused_kernel<<<NBLK, NTH, smem>>>(x, W, out);
}